// round 14
// baseline (speedup 1.0000x reference)
#include <cuda_runtime.h>
#include <math.h>
#include <float.h>

#define BB 64
#define QQ 900
#define TT 128
#define C1 14    // NUM_CLASSES+1
#define QP 912   // padded Q stride for the transposed prob table (16B aligned)
#define NC 4     // columns owned per thread in the Dijkstra loop

typedef unsigned long long u64;

// Scratch (static device globals; no allocation)
__device__ __align__(16) float g_probT[(size_t)BB*C1*QP];  // -softmax, [b][c][q]
__device__ float  g_lse[BB*QQ];
__device__ double g_basepart[BB*4];          // per-softmax-block sum of nll13
__device__ u64    g_ppart[BB*4*TT];          // packed partial row minima
__device__ float  g_partial[BB];
__device__ unsigned g_count = 0;

// ---- monotone float<->key packing:  key order == float order ----
__device__ __forceinline__ unsigned key_of(float f) {
    unsigned bb = __float_as_uint(f);
    return bb ^ ((unsigned)(-(int)(bb >> 31)) | 0x80000000u);
}
__device__ __forceinline__ float val_of(unsigned k) {
    unsigned m = (k >> 31) ? 0x80000000u : 0xFFFFFFFFu;
    return __uint_as_float(k ^ m);
}
__device__ __forceinline__ u64 packkj(float f, int j) {
    return ((u64)key_of(f) << 32) | (unsigned)j;
}
__device__ __forceinline__ u64 umin64(u64 a, u64 b) { return a < b ? a : b; }

// on-the-fly cost of (target t, query j): L1(boxes) + (-prob[label_t][j]).
// Must be byte-identical everywhere it is evaluated.
__device__ __forceinline__ float cost_el(float4 pq, float4 t4, float cc)
{
    return (fabsf(pq.x - t4.x) + fabsf(pq.y - t4.y)) +
           (fabsf(pq.z - t4.z) + fabsf(pq.w - t4.w)) + cc;
}

// ---------------------------------------------------------------------------
// Kernel 0: softmax -> probT + lse + nll13 partial  AND  partial row minima
// over this block's 256 queries (2 threads per target). grid (4, B) x 256.
// ---------------------------------------------------------------------------
__global__ void __launch_bounds__(256) softmax_kernel(
    const float* __restrict__ pc, const float* __restrict__ pb,
    const int* __restrict__ tl, const float* __restrict__ tb)
{
    int b   = blockIdx.y;
    int x   = blockIdx.x;
    int tid = threadIdx.x;
    int q   = x * 256 + tid;
    int lane = tid & 31, wid = tid >> 5;

    __shared__ float  sprob[C1][256];
    __shared__ float4 sbox[256];
    __shared__ float4 stb[TT];
    __shared__ int    slab[TT];
    __shared__ double red[8];

    if (tid < TT) {
        stb[tid]  = ((const float4*)tb)[b * TT + tid];
        slab[tid] = tl[b * TT + tid];
    }

    double base = 0.0;
    if (q < QQ) {
        const float* lg = pc + ((size_t)b * QQ + q) * C1;
        float l[C1];
        float m = -FLT_MAX;
        #pragma unroll
        for (int c = 0; c < C1; c++) { l[c] = lg[c]; m = fmaxf(m, l[c]); }
        float logit13 = l[13];
        float s = 0.f;
        #pragma unroll
        for (int c = 0; c < C1; c++) { l[c] = expf(l[c] - m); s += l[c]; }
        float inv = -1.0f / s;                       // negative probs
        float* dst = g_probT + (size_t)b * C1 * QP + q;
        #pragma unroll
        for (int c = 0; c < C1; c++) {
            float np = l[c] * inv;
            sprob[c][tid] = np;
            dst[(size_t)c * QP] = np;
        }
        float lse = m + logf(s);
        g_lse[b * QQ + q] = lse;
        base = (double)(lse - logit13);              // nll at class 13
        sbox[tid] = ((const float4*)pb)[b * QQ + q];
    }

    #pragma unroll
    for (int o = 16; o; o >>= 1) base += __shfl_down_sync(0xffffffffu, base, o);
    if (lane == 0) red[wid] = base;
    __syncthreads();
    if (tid == 0) {
        double s = 0.0;
        #pragma unroll
        for (int k = 0; k < 8; k++) s += red[k];
        g_basepart[b * 4 + x] = s;
    }

    // ---- partial row minima: thread pair (2t, 2t+1) scans this block's
    // queries for target t; halves combined with one shuffle ----
    int nq = QQ - x * 256; if (nq > 256) nq = 256;
    int t    = tid >> 1;
    int half = tid & 1;
    float4 t4 = stb[t];
    const float* prow = &sprob[slab[t]][0];

    float bv = FLT_MAX;
    int   bj = 0x7fffffff;
    int lo = half * 128;
    int hi = lo + 128; if (hi > nq) hi = nq;
    for (int ql = lo; ql < hi; ql++) {
        float c = cost_el(sbox[ql], t4, prow[ql]);
        if (c < bv) { bv = c; bj = x * 256 + ql; }
    }
    u64 pk = packkj(bv, bj);
    u64 ot = __shfl_down_sync(0xffffffffu, pk, 1);
    pk = umin64(pk, ot);
    if (half == 0) g_ppart[((size_t)b * 4 + x) * TT + t] = pk;
}

// ---------------------------------------------------------------------------
// Kernel 1: greedy matching + single-barrier Dijkstra augments with
// register-resident per-column state + fused losses + last-block finalize.
// Thread tid owns columns j = tid+1+256k.  One 256-thread block per batch.
// ---------------------------------------------------------------------------
__global__ void __launch_bounds__(256) hungarian_kernel(
    const float* __restrict__ pc, const float* __restrict__ pb,
    const int* __restrict__ tl, const float* __restrict__ tb,
    float* __restrict__ outp)
{
    int b = blockIdx.x;
    int tid = threadIdx.x;
    int lane = tid & 31, wid = tid >> 5;

    __shared__ float  u[TT + 1];
    __shared__ short  p[QQ + 1];        // p[j] = row assigned to col j (1-based)
    __shared__ short  way[QQ + 1];
    __shared__ int    claim[QQ + 1];
    __shared__ short  freerows[TT];
    __shared__ short  predq[TT];
    __shared__ float4 spb[QQ];
    __shared__ float4 stb[TT];
    __shared__ int    slab[TT];
    __shared__ int    s_nfree, s_last;
    __shared__ u64    redp[2][8];       // double-buffered packed argmin
    __shared__ double redd[8][3];
    __shared__ double sw[2];

    const float* probB = g_probT + (size_t)b * C1 * QP;

    for (int j = tid; j <= QQ; j += 256) { p[j] = 0; claim[j] = 0x7fffffff; }
    for (int k = tid; k < QQ; k += 256) spb[k] = ((const float4*)pb)[b * QQ + k];
    if (tid < TT) {
        stb[tid]  = ((const float4*)tb)[b * TT + tid];
        slab[tid] = tl[b * TT + tid];
    }
    if (tid == 0) s_nfree = 0;
    __syncthreads();

    // ---- per-thread owned-column registers ----
    int    jc[NC];
    bool   valid[NC];
    float4 boxreg[NC];
    float  vreg[NC];
    float  spcreg[NC];
    bool   usedreg[NC];
    #pragma unroll
    for (int k = 0; k < NC; k++) {
        jc[k] = tid + 1 + 256 * k;
        valid[k] = (jc[k] <= QQ);
        vreg[k] = 0.0f;
        if (valid[k]) boxreg[k] = spb[jc[k] - 1];
    }

    // ---- combine row-min partials; greedy matching on tight edges ----
    int myamin = -1;
    if (tid < TT) {
        const u64* pp = g_ppart + (size_t)b * 4 * TT + tid;
        u64 m = pp[0];
        m = umin64(m, pp[TT]);
        m = umin64(m, pp[2 * TT]);
        m = umin64(m, pp[3 * TT]);
        u[tid + 1] = val_of((unsigned)(m >> 32));
        myamin = (int)(unsigned)(m & 0xffffffffu);
        atomicMin(&claim[myamin + 1], tid);
    }
    __syncthreads();
    if (tid < TT) {
        int j = myamin + 1;
        if (claim[j] == tid) p[j] = (short)(tid + 1);
        else {
            int k = atomicAdd(&s_nfree, 1);
            freerows[k] = (short)(tid + 1);
        }
    }
    __syncthreads();
    int nfree = s_nfree;

    // ---- Dijkstra augment for each free row (ONE barrier per iteration) ----
    for (int fi = 0; fi < nfree; fi++) {
        int i = freerows[fi];
        #pragma unroll
        for (int k = 0; k < NC; k++) { spcreg[k] = FLT_MAX; usedreg[k] = false; }
        if (tid == 0) p[0] = (short)i;
        if (tid < 8) redp[0][tid] = packkj(0.0f, 0);    // seed: root col 0, dist 0
        __syncthreads();

        int buf = 0;
        float minF; int sink;
        while (1) {
            // every thread reduces the 8 packed entries itself
            u64 best = redp[buf][0];
            #pragma unroll
            for (int k = 1; k < 8; k++) best = umin64(best, redp[buf][k]);
            int   j1     = (int)(unsigned)(best & 0xffffffffu);
            float minval = val_of((unsigned)(best >> 32));
            int   i0     = p[j1];
            if (i0 == 0) { sink = j1; minF = minval; break; }   // augmenting sink

            float base = minval - u[i0];
            float4 t4 = stb[i0 - 1];
            const float* prow = probB + (size_t)slab[i0 - 1] * QP;

            // owner marks the newly committed column
            #pragma unroll
            for (int k = 0; k < NC; k++)
                if (valid[k] && jc[k] == j1) usedreg[k] = true;

            // prefetch scattered prob entries for live columns
            float cc[NC];
            #pragma unroll
            for (int k = 0; k < NC; k++)
                if (valid[k] && !usedreg[k]) cc[k] = prow[jc[k] - 1];

            u64 pk = ~0ull;
            #pragma unroll
            for (int k = 0; k < NC; k++) {
                if (valid[k] && !usedreg[k]) {
                    float cst = cost_el(boxreg[k], t4, cc[k]);
                    float r = base + cst - vreg[k];
                    if (r < spcreg[k]) { spcreg[k] = r; way[jc[k]] = (short)j1; }
                    pk = umin64(pk, packkj(spcreg[k], jc[k]));
                }
            }
            #pragma unroll
            for (int o = 16; o; o >>= 1)
                pk = umin64(pk, __shfl_down_sync(0xffffffffu, pk, o));
            if (lane == 0) redp[buf ^ 1][wid] = pk;
            __syncthreads();
            buf ^= 1;
        }

        // owner-side dual update over tree columns (distinct rows per column)
        #pragma unroll
        for (int k = 0; k < NC; k++) {
            if (valid[k] && usedreg[k]) {
                float d = minF - spcreg[k];
                u[p[jc[k]]] += d;
                vreg[k] -= d;
            }
        }
        if (tid == 0) u[i] += minF;     // virtual root col 0: p[0]=i, spc=0
        __syncthreads();

        if (tid == 0) {                 // augment along alternating path
            int j0 = sink;
            while (j0) {
                int jn = way[j0];
                p[j0] = p[jn];
                j0 = jn;
            }
        }
        __syncthreads();
    }

    // emit assignment
    for (int j = tid + 1; j <= QQ; j += 256) {
        int r = p[j];
        if (r > 0) predq[r - 1] = (short)(j - 1);
    }
    __syncthreads();

    // ---- fused per-batch losses ----
    double l1sum = 0.0, gsum = 0.0, cls = 0.0;
    if (tid < TT) {
        int t = tid;
        int q = predq[t];
        int lab = slab[t];
        float4 pq = spb[q];
        float4 t4 = stb[t];
        float px = pq.x, py = pq.y, pw = pq.z, ph = pq.w;
        float tx = t4.x, ty = t4.y, tw = t4.z, th = t4.w;

        l1sum = (double)(fabsf(px - tx) + fabsf(py - ty) +
                         fabsf(pw - tw) + fabsf(ph - th));

        float p1x = px - 0.5f * pw, p1y = py - 0.5f * ph;
        float p2x = px + 0.5f * pw, p2y = py + 0.5f * ph;
        float t1x = tx - 0.5f * tw, t1y = ty - 0.5f * th;
        float t2x = tx + 0.5f * tw, t2y = ty + 0.5f * th;
        float a1 = (p2x - p1x) * (p2y - p1y);
        float a2 = (t2x - t1x) * (t2y - t1y);
        float ltx = fmaxf(p1x, t1x), lty = fmaxf(p1y, t1y);
        float rbx = fminf(p2x, t2x), rby = fminf(p2y, t2y);
        float iw = fmaxf(rbx - ltx, 0.f), ih = fmaxf(rby - lty, 0.f);
        float inter = iw * ih;
        float uni = a1 + a2 - inter;
        float iou = inter / uni;
        float cx1 = fminf(p1x, t1x), cy1 = fminf(p1y, t1y);
        float cx2 = fmaxf(p2x, t2x), cy2 = fmaxf(p2y, t2y);
        float ac = (cx2 - cx1) * (cy2 - cy1);
        gsum = (double)(iou - (ac - uni) / ac);

        float lse = g_lse[b * QQ + q];
        const float* pcl = pc + ((size_t)b * QQ + q) * C1;
        float nll_lab = lse - pcl[lab];
        float nll13   = lse - pcl[13];
        cls = (double)nll_lab - 0.05 * (double)nll13;
    }

    #pragma unroll
    for (int o = 16; o; o >>= 1) {
        l1sum += __shfl_down_sync(0xffffffffu, l1sum, o);
        gsum  += __shfl_down_sync(0xffffffffu, gsum, o);
        cls   += __shfl_down_sync(0xffffffffu, cls, o);
    }
    if (lane == 0) { redd[wid][0] = l1sum; redd[wid][1] = gsum; redd[wid][2] = cls; }
    __syncthreads();
    if (tid == 0) {
        double a = 0, g = 0, c = 0;
        #pragma unroll
        for (int k = 0; k < 4; k++) { a += redd[k][0]; g += redd[k][1]; c += redd[k][2]; }
        double base = g_basepart[b*4+0] + g_basepart[b*4+1] +
                      g_basepart[b*4+2] + g_basepart[b*4+3];
        double clsum = 0.05 * base + c;
        double wsum  = 128.0 + 772.0 * 0.05;
        double l1mean = a / (double)(TT * 4);
        double bbox = 5.0 * l1mean + 2.0 * (1.0 - g / (double)TT);
        g_partial[b] = (float)(bbox + clsum / wsum);
        __threadfence();
        unsigned old = atomicAdd(&g_count, 1u);
        s_last = (old == BB - 1) ? 1 : 0;
    }
    __syncthreads();

    if (s_last) {
        __threadfence();   // acquire: all g_partial visible
        double s = (tid < BB) ? (double)g_partial[tid] : 0.0;
        #pragma unroll
        for (int o = 16; o; o >>= 1) s += __shfl_down_sync(0xffffffffu, s, o);
        if (tid < 64 && lane == 0) sw[wid] = s;
        __syncthreads();
        if (tid == 0) {
            outp[0] = (float)((sw[0] + sw[1]) / (double)(BB * TT));
            g_count = 0;   // reset for next graph replay
        }
    }
}

// ---------------------------------------------------------------------------
extern "C" void kernel_launch(void* const* d_in, const int* in_sizes, int n_in,
                              void* d_out, int out_size)
{
    const float* pc = (const float*)d_in[0];  // predicted_class [B,Q,14]
    const float* pb = (const float*)d_in[1];  // predicted_bbox  [B,Q,4]
    const int*   tl = (const int*)d_in[2];    // target_labels   [B,T]
    const float* tb = (const float*)d_in[3];  // target_boxes    [B,T,4]

    softmax_kernel<<<dim3(4, BB), 256>>>(pc, pb, tl, tb);
    hungarian_kernel<<<BB, 256>>>(pc, pb, tl, tb, (float*)d_out);
}

// round 15
// speedup vs baseline: 1.1064x; 1.1064x over previous
#include <cuda_runtime.h>
#include <math.h>
#include <float.h>

#define BB 64
#define QQ 900
#define TT 128
#define C1 14    // NUM_CLASSES+1
#define NCL 13   // label range 0..12
#define QP 912   // padded Q stride (16B aligned)
#define NC 4     // columns owned per thread in the Dijkstra loop

typedef unsigned long long u64;

// Scratch (static device globals; no allocation)
__device__ __align__(16) float g_probT[(size_t)BB*C1*QP];  // -softmax, [b][c][q]
__device__ float  g_lse[BB*QQ];
__device__ double g_basepart[BB*4];          // per-softmax-block sum of nll13
__device__ u64    g_ppart[BB*4*TT];          // packed partial row minima
__device__ float  g_partial[BB];
__device__ unsigned g_count = 0;

// ---- monotone float<->key packing:  key order == float order ----
__device__ __forceinline__ unsigned key_of(float f) {
    unsigned bb = __float_as_uint(f);
    return bb ^ ((unsigned)(-(int)(bb >> 31)) | 0x80000000u);
}
__device__ __forceinline__ float val_of(unsigned k) {
    unsigned m = (k >> 31) ? 0x80000000u : 0xFFFFFFFFu;
    return __uint_as_float(k ^ m);
}
__device__ __forceinline__ u64 packkj(float f, int j) {
    return ((u64)key_of(f) << 32) | (unsigned)j;
}
__device__ __forceinline__ u64 umin64(u64 a, u64 b) { return a < b ? a : b; }

// on-the-fly cost of (target t, query j): L1(boxes) + (-prob[label_t][j]).
// Must be byte-identical everywhere it is evaluated.
__device__ __forceinline__ float cost_el(float4 pq, float4 t4, float cc)
{
    return (fabsf(pq.x - t4.x) + fabsf(pq.y - t4.y)) +
           (fabsf(pq.z - t4.z) + fabsf(pq.w - t4.w)) + cc;
}

// ---------------------------------------------------------------------------
// Kernel 0: softmax -> probT + lse + nll13 partial  AND  partial row minima
// over this block's 256 queries (2 threads per target). grid (4, B) x 256.
// ---------------------------------------------------------------------------
__global__ void __launch_bounds__(256) softmax_kernel(
    const float* __restrict__ pc, const float* __restrict__ pb,
    const int* __restrict__ tl, const float* __restrict__ tb)
{
    int b   = blockIdx.y;
    int x   = blockIdx.x;
    int tid = threadIdx.x;
    int q   = x * 256 + tid;
    int lane = tid & 31, wid = tid >> 5;

    __shared__ float  sprob[C1][256];
    __shared__ float4 sbox[256];
    __shared__ float4 stb[TT];
    __shared__ int    slab[TT];
    __shared__ double red[8];

    if (tid < TT) {
        stb[tid]  = ((const float4*)tb)[b * TT + tid];
        slab[tid] = tl[b * TT + tid];
    }

    double base = 0.0;
    if (q < QQ) {
        const float* lg = pc + ((size_t)b * QQ + q) * C1;
        float l[C1];
        float m = -FLT_MAX;
        #pragma unroll
        for (int c = 0; c < C1; c++) { l[c] = lg[c]; m = fmaxf(m, l[c]); }
        float logit13 = l[13];
        float s = 0.f;
        #pragma unroll
        for (int c = 0; c < C1; c++) { l[c] = expf(l[c] - m); s += l[c]; }
        float inv = -1.0f / s;                       // negative probs
        float* dst = g_probT + (size_t)b * C1 * QP + q;
        #pragma unroll
        for (int c = 0; c < C1; c++) {
            float np = l[c] * inv;
            sprob[c][tid] = np;
            dst[(size_t)c * QP] = np;
        }
        float lse = m + logf(s);
        g_lse[b * QQ + q] = lse;
        base = (double)(lse - logit13);              // nll at class 13
        sbox[tid] = ((const float4*)pb)[b * QQ + q];
    }

    #pragma unroll
    for (int o = 16; o; o >>= 1) base += __shfl_down_sync(0xffffffffu, base, o);
    if (lane == 0) red[wid] = base;
    __syncthreads();
    if (tid == 0) {
        double s = 0.0;
        #pragma unroll
        for (int k = 0; k < 8; k++) s += red[k];
        g_basepart[b * 4 + x] = s;
    }

    // ---- partial row minima: thread pair (2t, 2t+1) scans this block's
    // queries for target t; halves combined with one shuffle ----
    int nq = QQ - x * 256; if (nq > 256) nq = 256;
    int t    = tid >> 1;
    int half = tid & 1;
    float4 t4 = stb[t];
    const float* prow = &sprob[slab[t]][0];

    float bv = FLT_MAX;
    int   bj = 0x7fffffff;
    int lo = half * 128;
    int hi = lo + 128; if (hi > nq) hi = nq;
    for (int ql = lo; ql < hi; ql++) {
        float c = cost_el(sbox[ql], t4, prow[ql]);
        if (c < bv) { bv = c; bj = x * 256 + ql; }
    }
    u64 pk = packkj(bv, bj);
    u64 ot = __shfl_down_sync(0xffffffffu, pk, 1);
    pk = umin64(pk, ot);
    if (half == 0) g_ppart[((size_t)b * 4 + x) * TT + t] = pk;
}

// ---------------------------------------------------------------------------
// Kernel 1: greedy matching + single-barrier Dijkstra augments with
// register-resident per-column state and a SHARED-memory prob table
// (13 class rows x 912) + fused losses + last-block finalize.
// Thread tid owns columns j = tid+1+256k.  One 256-thread block per batch.
// Dynamic smem layout: [ probS: NCL*QP floats ][ spb: QQ float4 ]
// ---------------------------------------------------------------------------
extern __shared__ float dynsm[];

__global__ void __launch_bounds__(256) hungarian_kernel(
    const float* __restrict__ pc, const float* __restrict__ pb,
    const int* __restrict__ tl, const float* __restrict__ tb,
    float* __restrict__ outp)
{
    int b = blockIdx.x;
    int tid = threadIdx.x;
    int lane = tid & 31, wid = tid >> 5;

    float*  probS = dynsm;                                // NCL*QP floats
    float4* spb   = (float4*)(dynsm + NCL * QP);          // QQ float4

    __shared__ float  u[TT + 1];
    __shared__ short  p[QQ + 1];        // p[j] = row assigned to col j (1-based)
    __shared__ short  way[QQ + 1];
    __shared__ int    claim[QQ + 1];
    __shared__ short  freerows[TT];
    __shared__ short  predq[TT];
    __shared__ float4 stb[TT];
    __shared__ int    slab[TT];
    __shared__ int    s_nfree, s_last;
    __shared__ u64    redp[2][8];       // double-buffered packed argmin
    __shared__ double redd[8][3];
    __shared__ double sw[2];

    // ---- cooperative loads ----
    {
        const float4* src = (const float4*)(g_probT + (size_t)b * C1 * QP);
        float4* dst = (float4*)probS;
        const int n4 = NCL * QP / 4;                       // 2964 float4s
        for (int k = tid; k < n4; k += 256) dst[k] = src[k];
    }
    for (int j = tid; j <= QQ; j += 256) { p[j] = 0; claim[j] = 0x7fffffff; }
    for (int k = tid; k < QQ; k += 256) spb[k] = ((const float4*)pb)[b * QQ + k];
    if (tid < TT) {
        stb[tid]  = ((const float4*)tb)[b * TT + tid];
        slab[tid] = tl[b * TT + tid];
    }
    if (tid == 0) s_nfree = 0;
    __syncthreads();

    // ---- per-thread owned-column registers ----
    int    jc[NC];
    bool   valid[NC];
    float4 boxreg[NC];
    float  vreg[NC];
    float  spcreg[NC];
    bool   usedreg[NC];
    #pragma unroll
    for (int k = 0; k < NC; k++) {
        jc[k] = tid + 1 + 256 * k;
        valid[k] = (jc[k] <= QQ);
        vreg[k] = 0.0f;
        if (valid[k]) boxreg[k] = spb[jc[k] - 1];
    }

    // ---- combine row-min partials; greedy matching on tight edges ----
    int myamin = -1;
    if (tid < TT) {
        const u64* pp = g_ppart + (size_t)b * 4 * TT + tid;
        u64 m = pp[0];
        m = umin64(m, pp[TT]);
        m = umin64(m, pp[2 * TT]);
        m = umin64(m, pp[3 * TT]);
        u[tid + 1] = val_of((unsigned)(m >> 32));
        myamin = (int)(unsigned)(m & 0xffffffffu);
        atomicMin(&claim[myamin + 1], tid);
    }
    __syncthreads();
    if (tid < TT) {
        int j = myamin + 1;
        if (claim[j] == tid) p[j] = (short)(tid + 1);
        else {
            int k = atomicAdd(&s_nfree, 1);
            freerows[k] = (short)(tid + 1);
        }
    }
    __syncthreads();
    int nfree = s_nfree;

    // ---- Dijkstra augment for each free row (ONE barrier per iteration) ----
    for (int fi = 0; fi < nfree; fi++) {
        int i = freerows[fi];
        #pragma unroll
        for (int k = 0; k < NC; k++) { spcreg[k] = FLT_MAX; usedreg[k] = false; }
        if (tid == 0) p[0] = (short)i;
        if (tid < 8) redp[0][tid] = packkj(0.0f, 0);    // seed: root col 0, dist 0
        __syncthreads();

        int buf = 0;
        float minF; int sink;
        while (1) {
            // every thread reduces the 8 packed entries itself
            u64 best = redp[buf][0];
            #pragma unroll
            for (int k = 1; k < 8; k++) best = umin64(best, redp[buf][k]);
            int   j1     = (int)(unsigned)(best & 0xffffffffu);
            float minval = val_of((unsigned)(best >> 32));
            int   i0     = p[j1];
            if (i0 == 0) { sink = j1; minF = minval; break; }   // augmenting sink

            float base = minval - u[i0];
            float4 t4 = stb[i0 - 1];
            const float* prow = probS + slab[i0 - 1] * QP;

            // owner marks the newly committed column
            #pragma unroll
            for (int k = 0; k < NC; k++)
                if (valid[k] && jc[k] == j1) usedreg[k] = true;

            // shared-memory prob fetch for live columns (LDS, not LDG)
            float cc[NC];
            #pragma unroll
            for (int k = 0; k < NC; k++)
                if (valid[k] && !usedreg[k]) cc[k] = prow[jc[k] - 1];

            u64 pk = ~0ull;
            #pragma unroll
            for (int k = 0; k < NC; k++) {
                if (valid[k] && !usedreg[k]) {
                    float cst = cost_el(boxreg[k], t4, cc[k]);
                    float r = base + cst - vreg[k];
                    if (r < spcreg[k]) { spcreg[k] = r; way[jc[k]] = (short)j1; }
                    pk = umin64(pk, packkj(spcreg[k], jc[k]));
                }
            }
            #pragma unroll
            for (int o = 16; o; o >>= 1)
                pk = umin64(pk, __shfl_down_sync(0xffffffffu, pk, o));
            if (lane == 0) redp[buf ^ 1][wid] = pk;
            __syncthreads();
            buf ^= 1;
        }

        // owner-side dual update over tree columns (distinct rows per column)
        #pragma unroll
        for (int k = 0; k < NC; k++) {
            if (valid[k] && usedreg[k]) {
                float d = minF - spcreg[k];
                u[p[jc[k]]] += d;
                vreg[k] -= d;
            }
        }
        if (tid == 0) u[i] += minF;     // virtual root col 0: p[0]=i, spc=0
        __syncthreads();

        if (tid == 0) {                 // augment along alternating path
            int j0 = sink;
            while (j0) {
                int jn = way[j0];
                p[j0] = p[jn];
                j0 = jn;
            }
        }
        __syncthreads();
    }

    // emit assignment
    for (int j = tid + 1; j <= QQ; j += 256) {
        int r = p[j];
        if (r > 0) predq[r - 1] = (short)(j - 1);
    }
    __syncthreads();

    // ---- fused per-batch losses ----
    double l1sum = 0.0, gsum = 0.0, cls = 0.0;
    if (tid < TT) {
        int t = tid;
        int q = predq[t];
        int lab = slab[t];
        float4 pq = spb[q];
        float4 t4 = stb[t];
        float px = pq.x, py = pq.y, pw = pq.z, ph = pq.w;
        float tx = t4.x, ty = t4.y, tw = t4.z, th = t4.w;

        l1sum = (double)(fabsf(px - tx) + fabsf(py - ty) +
                         fabsf(pw - tw) + fabsf(ph - th));

        float p1x = px - 0.5f * pw, p1y = py - 0.5f * ph;
        float p2x = px + 0.5f * pw, p2y = py + 0.5f * ph;
        float t1x = tx - 0.5f * tw, t1y = ty - 0.5f * th;
        float t2x = tx + 0.5f * tw, t2y = ty + 0.5f * th;
        float a1 = (p2x - p1x) * (p2y - p1y);
        float a2 = (t2x - t1x) * (t2y - t1y);
        float ltx = fmaxf(p1x, t1x), lty = fmaxf(p1y, t1y);
        float rbx = fminf(p2x, t2x), rby = fminf(p2y, t2y);
        float iw = fmaxf(rbx - ltx, 0.f), ih = fmaxf(rby - lty, 0.f);
        float inter = iw * ih;
        float uni = a1 + a2 - inter;
        float iou = inter / uni;
        float cx1 = fminf(p1x, t1x), cy1 = fminf(p1y, t1y);
        float cx2 = fmaxf(p2x, t2x), cy2 = fmaxf(p2y, t2y);
        float ac = (cx2 - cx1) * (cy2 - cy1);
        gsum = (double)(iou - (ac - uni) / ac);

        float lse = g_lse[b * QQ + q];
        const float* pcl = pc + ((size_t)b * QQ + q) * C1;
        float nll_lab = lse - pcl[lab];
        float nll13   = lse - pcl[13];
        cls = (double)nll_lab - 0.05 * (double)nll13;
    }

    #pragma unroll
    for (int o = 16; o; o >>= 1) {
        l1sum += __shfl_down_sync(0xffffffffu, l1sum, o);
        gsum  += __shfl_down_sync(0xffffffffu, gsum, o);
        cls   += __shfl_down_sync(0xffffffffu, cls, o);
    }
    if (lane == 0) { redd[wid][0] = l1sum; redd[wid][1] = gsum; redd[wid][2] = cls; }
    __syncthreads();
    if (tid == 0) {
        double a = 0, g = 0, c = 0;
        #pragma unroll
        for (int k = 0; k < 4; k++) { a += redd[k][0]; g += redd[k][1]; c += redd[k][2]; }
        double base = g_basepart[b*4+0] + g_basepart[b*4+1] +
                      g_basepart[b*4+2] + g_basepart[b*4+3];
        double clsum = 0.05 * base + c;
        double wsum  = 128.0 + 772.0 * 0.05;
        double l1mean = a / (double)(TT * 4);
        double bbox = 5.0 * l1mean + 2.0 * (1.0 - g / (double)TT);
        g_partial[b] = (float)(bbox + clsum / wsum);
        __threadfence();
        unsigned old = atomicAdd(&g_count, 1u);
        s_last = (old == BB - 1) ? 1 : 0;
    }
    __syncthreads();

    if (s_last) {
        __threadfence();   // acquire: all g_partial visible
        double s = (tid < BB) ? (double)g_partial[tid] : 0.0;
        #pragma unroll
        for (int o = 16; o; o >>= 1) s += __shfl_down_sync(0xffffffffu, s, o);
        if (tid < 64 && lane == 0) sw[wid] = s;
        __syncthreads();
        if (tid == 0) {
            outp[0] = (float)((sw[0] + sw[1]) / (double)(BB * TT));
            g_count = 0;   // reset for next graph replay
        }
    }
}

// ---------------------------------------------------------------------------
extern "C" void kernel_launch(void* const* d_in, const int* in_sizes, int n_in,
                              void* d_out, int out_size)
{
    const float* pc = (const float*)d_in[0];  // predicted_class [B,Q,14]
    const float* pb = (const float*)d_in[1];  // predicted_bbox  [B,Q,4]
    const int*   tl = (const int*)d_in[2];    // target_labels   [B,T]
    const float* tb = (const float*)d_in[3];  // target_boxes    [B,T,4]

    const int dynbytes = NCL * QP * 4 + QQ * 16;   // probS + spb = 61824 B
    static int attr_done = 0;
    if (!attr_done) {   // idempotent attribute set (not a work guard)
        cudaFuncSetAttribute(hungarian_kernel,
                             cudaFuncAttributeMaxDynamicSharedMemorySize, dynbytes);
        attr_done = 1;
    }

    softmax_kernel<<<dim3(4, BB), 256>>>(pc, pb, tl, tb);
    hungarian_kernel<<<BB, 256, dynbytes>>>(pc, pb, tl, tb, (float*)d_out);
}